// round 10
// baseline (speedup 1.0000x reference)
#include <cuda_runtime.h>
#include <cuda_fp16.h>
#include <math.h>
#include <stdint.h>

typedef unsigned long long u64;

// ---------------- problem constants ----------------
#define NB   128
#define SSEG 20
#define DDICT 1000
#define LSEG 200
#define OUTDIM 62      // 2 + 3*20

// ---------------- f32x2 helpers ----------------
__device__ __forceinline__ u64 pack2(float a, float b) {
    u64 r; asm("mov.b64 %0, {%1, %2};" : "=l"(r) : "f"(a), "f"(b)); return r;
}
__device__ __forceinline__ u64 fma2(u64 a, u64 b, u64 c) {
    u64 d; asm("fma.rn.f32x2 %0, %1, %2, %3;" : "=l"(d) : "l"(a), "l"(b), "l"(c)); return d;
}
__device__ __forceinline__ void unpack2(u64 v, float& lo, float& hi) {
    asm("mov.b64 {%0, %1}, %2;" : "=f"(lo), "=f"(hi) : "l"(v));
}

// ---------------- mma / ldmatrix helpers ----------------
__device__ __forceinline__ void mma16816(float* d, const uint32_t* a, const uint32_t* b) {
    asm volatile(
        "mma.sync.aligned.m16n8k16.row.col.f32.f16.f16.f32 "
        "{%0,%1,%2,%3}, {%4,%5,%6,%7}, {%8,%9}, {%0,%1,%2,%3};"
        : "+f"(d[0]), "+f"(d[1]), "+f"(d[2]), "+f"(d[3])
        : "r"(a[0]), "r"(a[1]), "r"(a[2]), "r"(a[3]), "r"(b[0]), "r"(b[1]));
}
#define LDM_X4(r0,r1,r2,r3,a) \
    asm volatile("ldmatrix.sync.aligned.m8n8.x4.shared.b16 {%0,%1,%2,%3}, [%4];" \
        : "=r"(r0),"=r"(r1),"=r"(r2),"=r"(r3) : "r"(a))
#define LDM_X2(r0,r1,a) \
    asm volatile("ldmatrix.sync.aligned.m8n8.x2.shared.b16 {%0,%1}, [%2];" \
        : "=r"(r0),"=r"(r1) : "r"(a))
__device__ __forceinline__ uint32_t smem_u32(const void* p) {
    uint32_t a;
    asm("{ .reg .u64 t; cvta.to.shared.u64 t, %1; cvt.u32.u64 %0, t; }" : "=r"(a) : "l"(p));
    return a;
}
// pack f32 -> half2{hi, lo} as u32
__device__ __forceinline__ uint32_t split16(float v) {
    __half hi = __float2half_rn(v);
    __half lo = __float2half_rn(v - __half2float(hi));
    return (uint32_t)__half_as_ushort(hi) | ((uint32_t)__half_as_ushort(lo) << 16);
}

// ---------------- scratch (device globals; activations packed half2{hi,lo}) ------------
__device__ uint32_t g_h1p[(size_t)NB*64*49*49 + 8192];
__device__ uint32_t g_h2p[(size_t)NB*128*23*23 + 8192];
__device__ uint32_t g_h3p[(size_t)NB*256*10*10 + 8192];
__device__ float    g_h4 [(size_t)NB*512*4*4];
__device__ float g_a1[NB*2048];
__device__ float g_a2[NB*2048];
__device__ float g_part[2*NB*2048];
__device__ float g_p [NB*OUTDIM];
__device__ float g_w1k[64*3*9];
// fp16-split weights: [kh][co][kw*CIN+ci]
__device__ __align__(16) __half g_w2h[9*128*64],  g_w2l[9*128*64];
__device__ __align__(16) __half g_w3h[9*256*128], g_w3l[9*256*128];
__device__ __align__(16) __half g_w4h[9*512*256], g_w4l[9*512*256];

// ---------------- weight repack for scalar conv1 ----------------
__global__ void repack_wk(const float* __restrict__ w, float* __restrict__ wk, int CIN, int COUT)
{
    int i = blockIdx.x * blockDim.x + threadIdx.x;
    int total = COUT * CIN * 9;
    if (i >= total) return;
    int c  = i % 8;
    int k  = (i / 8) % 9;
    int ci = (i / 72) % CIN;
    int cg = i / (72 * CIN);
    wk[i] = w[((size_t)(cg * 8 + c) * CIN + ci) * 9 + k];
}

// ---------------- weight repack + fp16 split: -> [kh][co][kw*CIN+ci] ----------------
__global__ void repack_h2(const float* __restrict__ w, __half* __restrict__ whi,
                          __half* __restrict__ wlo, int CIN, int COUT)
{
    int i = blockIdx.x * blockDim.x + threadIdx.x;
    int tot = COUT * CIN * 9;
    if (i >= tot) return;
    int kw = i % 3, kh = (i / 3) % 3, ci = (i / 9) % CIN, co = i / (9 * CIN);
    float v = w[i];
    __half hi = __float2half_rn(v);
    __half lo = __float2half_rn(v - __half2float(hi));
    size_t d = (((size_t)kh * COUT + co) * 3 + kw) * CIN + ci;
    whi[d] = hi;
    wlo[d] = lo;
}

// ---------------- fp16-split mma.sync fused conv3x3 + bias + maxpool2 + relu ------------
// Input activations pre-split packed half2{hi,lo}. ldmatrix fragment loads.
// OUTH=1: write packed half2 output; OUTH=0: write f32 (for FC consumption).
template<int CIN, int H, int W, int COUT, int ROWS, int OUTH>
__global__ __launch_bounds__(256, 2)
void conv_mma(const uint32_t* __restrict__ src, const __half* __restrict__ whi,
              const __half* __restrict__ wlo, const float* __restrict__ bias,
              void* __restrict__ dstv)
{
    constexpr int HW  = H * W;
    constexpr int KCH = CIN / 32;
    constexpr int NCH = 9 * KCH;
    constexpr int PR  = ROWS / 2;
    constexpr int PWW = (W - 2) / 2;
    constexpr int PHH = (H - 2) / 2;
    constexpr int ST2 = 40;             // halves per smem tile row (32 k + 8 pad) = 80B
    constexpr int TILE = 128 * ST2;
    constexpr int EST = 132;            // epilogue row stride (floats)

    extern __shared__ __align__(16) char smraw[];
    uint16_t* Ah = (uint16_t*)smraw;             // [128][ST2]
    uint16_t* Al = Ah + TILE;
    uint16_t* Bh = Ah + 2 * TILE;
    uint16_t* Bl = Ah + 3 * TILE;
    float*    eps = (float*)smraw;               // epilogue overlay [128][EST]

    const uint32_t AhS = smem_u32(Ah);
    const uint32_t AlS = smem_u32(Al);
    const uint32_t BhS = smem_u32(Bh);
    const uint32_t BlS = smem_u32(Bl);

    const int tid  = threadIdx.x;
    const int wid  = tid >> 5;
    const int lane = tid & 31;
    const int l4   = lane >> 2;
    const int lm   = lane & 3;

    const int img = blockIdx.y;
    const int r0  = blockIdx.x * ROWS;
    const int m0  = blockIdx.z * 128;
    const uint32_t* ib = src + (size_t)img * CIN * HW + r0 * W;

    const int co   = tid & 127;
    const int half = tid >> 7;
    const int bn   = tid & 127;

    const int co0w = (wid >> 1) * 32;
    const int n0w  = (wid & 1) * 64;

    // precomputed ldmatrix lane addresses (byte offsets into tiles)
    const uint32_t aoff = (uint32_t)(((lane & 15)) * ST2 + (lane >> 4) * 8) * 2;
    const uint32_t boff = (uint32_t)(((lane & 7))  * ST2 + ((lane >> 3) & 1) * 8) * 2;

    float acc[2][8][4];
    #pragma unroll
    for (int mb = 0; mb < 2; mb++)
        #pragma unroll
        for (int nb = 0; nb < 8; nb++)
            #pragma unroll
            for (int j = 0; j < 4; j++) acc[mb][nb][j] = 0.0f;

    for (int s = 0; s < NCH; s++) {
        int cc  = s % KCH;
        int kwv = (s / KCH) % 3;
        int khv = s / (3 * KCH);
        int ci0 = cc * 32;

        if (s > 0) __syncthreads();

        // ---- A tile [co128][k32]: pre-split weight halves, 16 each via 2x uint4 ----
        {
            size_t off = (((size_t)khv * COUT + m0 + co) * 3 + kwv) * CIN + ci0 + half * 16;
            uint4 vh0 = *(const uint4*)(whi + off);
            uint4 vh1 = *(const uint4*)(whi + off + 8);
            uint4 vl0 = *(const uint4*)(wlo + off);
            uint4 vl1 = *(const uint4*)(wlo + off + 8);
            uint32_t sa = co * ST2 + half * 16;
            *(uint4*)(Ah + sa)     = vh0;
            *(uint4*)(Ah + sa + 8) = vh1;
            *(uint4*)(Al + sa)     = vl0;
            *(uint4*)(Al + sa + 8) = vl1;
        }
        // ---- B tile [n128][k32]: pure copy of pre-split activations ----
        {
            const uint32_t* bp = ib + bn + khv * W + kwv;
            #pragma unroll
            for (int i = 0; i < 16; i++) {
                int k = half * 16 + i;
                uint32_t v = __ldg(bp + (size_t)(ci0 + k) * HW);
                Bh[bn * ST2 + k] = (uint16_t)v;
                Bl[bn * ST2 + k] = (uint16_t)(v >> 16);
            }
        }
        __syncthreads();

        #pragma unroll
        for (int ks = 0; ks < 2; ks++) {
            uint32_t kbase = (uint32_t)(ks * 16) * 2;   // byte offset of k-chunk
            uint32_t ah[2][4], al[2][4];
            #pragma unroll
            for (int mb = 0; mb < 2; mb++) {
                uint32_t ra = (uint32_t)((co0w + mb * 16) * ST2) * 2 + aoff + kbase;
                LDM_X4(ah[mb][0], ah[mb][1], ah[mb][2], ah[mb][3], AhS + ra);
                LDM_X4(al[mb][0], al[mb][1], al[mb][2], al[mb][3], AlS + ra);
            }
            #pragma unroll
            for (int nb = 0; nb < 8; nb++) {
                uint32_t rb = (uint32_t)((n0w + nb * 8) * ST2) * 2 + boff + kbase;
                uint32_t bh[2], bl[2];
                LDM_X2(bh[0], bh[1], BhS + rb);
                LDM_X2(bl[0], bl[1], BlS + rb);
                #pragma unroll
                for (int mb = 0; mb < 2; mb++) {
                    mma16816(acc[mb][nb], ah[mb], bh);
                    mma16816(acc[mb][nb], ah[mb], bl);
                    mma16816(acc[mb][nb], al[mb], bh);
                }
            }
        }
    }

    __syncthreads();   // reuse smem for epilogue

    #pragma unroll
    for (int mb = 0; mb < 2; mb++) {
        #pragma unroll
        for (int nb = 0; nb < 8; nb++) {
            int n = n0w + nb * 8 + 2 * lm;
            int c_lo = co0w + mb * 16 + l4;
            *(float2*)&eps[c_lo * EST + n]       = make_float2(acc[mb][nb][0], acc[mb][nb][1]);
            *(float2*)&eps[(c_lo + 8) * EST + n] = make_float2(acc[mb][nb][2], acc[mb][nb][3]);
        }
    }
    __syncthreads();

    // ---- pool + bias + relu ----
    for (int t = tid; t < 128 * PR * PWW; t += 256) {
        int pw = t % PWW;
        int r  = t / PWW;
        int pr = r % PR;
        int c  = r / PR;
        int c0 = (2 * pr) * W + 2 * pw;
        const float* e = eps + c * EST;
        float v = fmaxf(fmaxf(e[c0], e[c0 + 1]), fmaxf(e[c0 + W], e[c0 + W + 1]))
                  + __ldg(bias + m0 + c);
        v = fmaxf(v, 0.0f);
        size_t oidx = (((size_t)img * COUT + m0 + c) * PHH + (r0 >> 1) + pr) * PWW + pw;
        if (OUTH) ((uint32_t*)dstv)[oidx] = split16(v);
        else      ((float*)dstv)[oidx]    = v;
    }
}

// ---------------- scalar conv stage 1 (CIN=3) — FFMA2, packed-half2 output ----------------
template<int CIN, int HIN, int WIN, int HP, int WP, int COUT>
__global__ __launch_bounds__(256)
void conv_pool_relu2(const float* __restrict__ in,
                     const float* __restrict__ wk,
                     const float* __restrict__ bias,
                     uint32_t* __restrict__ out)
{
    constexpr int COG = COUT / 8;
    int idx = blockIdx.x * blockDim.x + threadIdx.x;
    const int total = NB * COG * HP * WP;
    if (idx >= total) return;

    int pw = idx % WP;  int t = idx / WP;
    int ph = t % HP;    t /= HP;
    int cg = t % COG;   t /= COG;
    int b  = t;
    int co0 = cg * 8;

    u64 acc2[4][4];
    #pragma unroll
    for (int p = 0; p < 4; p++)
        #pragma unroll
        for (int j = 0; j < 4; j++) acc2[p][j] = 0ull;

    const float* inb = in + ((size_t)b * CIN * HIN + 2 * ph) * WIN + 2 * pw;
    const ulonglong2* __restrict__ wbase =
        reinterpret_cast<const ulonglong2*>(wk + (size_t)cg * CIN * 72);

    for (int ci = 0; ci < CIN; ci++) {
        const float* ip = inb + (size_t)ci * HIN * WIN;
        u64 xx[16];
        #pragma unroll
        for (int r = 0; r < 4; r++)
            #pragma unroll
            for (int c = 0; c < 4; c++) {
                float v = __ldg(ip + r * WIN + c);
                xx[r * 4 + c] = pack2(v, v);
            }
        const ulonglong2* wp = wbase + (size_t)ci * 18;
        #pragma unroll
        for (int k = 0; k < 9; k++) {
            ulonglong2 wA = wp[2 * k];
            ulonglong2 wB = wp[2 * k + 1];
            u64 wpair[4] = {wA.x, wA.y, wB.x, wB.y};
            int kh = k / 3, kw = k % 3;
            #pragma unroll
            for (int p = 0; p < 4; p++)
                #pragma unroll
                for (int dy = 0; dy < 2; dy++)
                    #pragma unroll
                    for (int dx = 0; dx < 2; dx++)
                        acc2[p][dy * 2 + dx] =
                            fma2(xx[(dy + kh) * 4 + dx + kw], wpair[p], acc2[p][dy * 2 + dx]);
        }
    }

    #pragma unroll
    for (int p = 0; p < 4; p++) {
        float l0, h0, l1, h1, l2, h2, l3, h3;
        unpack2(acc2[p][0], l0, h0);
        unpack2(acc2[p][1], l1, h1);
        unpack2(acc2[p][2], l2, h2);
        unpack2(acc2[p][3], l3, h3);
        float mlo = fmaxf(fmaxf(l0, l1), fmaxf(l2, l3)) + __ldg(bias + co0 + 2 * p);
        float mhi = fmaxf(fmaxf(h0, h1), fmaxf(h2, h3)) + __ldg(bias + co0 + 2 * p + 1);
        size_t o0 = (((size_t)b * COUT + co0 + 2 * p) * HP + ph) * WP + pw;
        out[o0]                   = split16(fmaxf(mlo, 0.0f));
        out[o0 + (size_t)HP * WP] = split16(fmaxf(mhi, 0.0f));
    }
}

// ---------------- FFMA2 tiled SGEMM ----------------
template<int ACT>
__global__ __launch_bounds__(256)
void gemm64v2(const float* __restrict__ A, const float* __restrict__ B,
              const float* __restrict__ bias, float* __restrict__ C,
              int M, int N, int K)
{
    const int BM = 64, BN = 64, BK = 16;
    __shared__ float As[BK][BM + 1];
    __shared__ float Bs[BK][BN];
    int tx = threadIdx.x % 16, ty = threadIdx.x / 16;
    int m0 = blockIdx.y * BM, n0 = blockIdx.x * BN;

    u64 acc[4][2] = {};
    for (int kk = 0; kk < K; kk += BK) {
        #pragma unroll
        for (int i = 0; i < 4; i++) {
            int l = threadIdx.x + i * 256;
            int m = l / 16, k = l % 16;
            As[k][m] = A[(size_t)(m0 + m) * K + kk + k];
        }
        #pragma unroll
        for (int i = 0; i < 4; i++) {
            int l = threadIdx.x + i * 256;
            int n = l % 64, k = l / 64;
            Bs[k][n] = B[(size_t)(kk + k) * N + n0 + n];
        }
        __syncthreads();
        #pragma unroll
        for (int k = 0; k < BK; k++) {
            u64 b0 = *reinterpret_cast<const u64*>(&Bs[k][tx * 4]);
            u64 b1 = *reinterpret_cast<const u64*>(&Bs[k][tx * 4 + 2]);
            #pragma unroll
            for (int i = 0; i < 4; i++) {
                float a = As[k][ty * 4 + i];
                u64 ap = pack2(a, a);
                acc[i][0] = fma2(ap, b0, acc[i][0]);
                acc[i][1] = fma2(ap, b1, acc[i][1]);
            }
        }
        __syncthreads();
    }

    #pragma unroll
    for (int i = 0; i < 4; i++) {
        int m = m0 + ty * 4 + i;
        #pragma unroll
        for (int j = 0; j < 2; j++) {
            float lo, hi;
            unpack2(acc[i][j], lo, hi);
            int n = n0 + tx * 4 + j * 2;
            float v0 = lo + __ldg(bias + n);
            float v1 = hi + __ldg(bias + n + 1);
            if (ACT == 1) { v0 = tanhf(v0); v1 = tanhf(v1); }
            C[(size_t)m * N + n]     = v0;
            C[(size_t)m * N + n + 1] = v1;
        }
    }
}

// ---------------- split-K partial GEMM ----------------
__global__ __launch_bounds__(256)
void gemm64_part(const float* __restrict__ A, const float* __restrict__ B,
                 float* __restrict__ Cpart, int M, int N, int K, int Ks)
{
    const int BM = 64, BN = 64, BK = 16;
    __shared__ float As[BK][BM + 1];
    __shared__ float Bs[BK][BN];
    int tx = threadIdx.x % 16, ty = threadIdx.x / 16;
    int m0 = blockIdx.y * BM, n0 = blockIdx.x * BN;
    int z = blockIdx.z;
    int k0 = z * Ks;
    float* Cz = Cpart + (size_t)z * M * N;

    u64 acc[4][2] = {};
    for (int kk = k0; kk < k0 + Ks; kk += BK) {
        #pragma unroll
        for (int i = 0; i < 4; i++) {
            int l = threadIdx.x + i * 256;
            int m = l / 16, k = l % 16;
            As[k][m] = A[(size_t)(m0 + m) * K + kk + k];
        }
        #pragma unroll
        for (int i = 0; i < 4; i++) {
            int l = threadIdx.x + i * 256;
            int n = l % 64, k = l / 64;
            Bs[k][n] = B[(size_t)(kk + k) * N + n0 + n];
        }
        __syncthreads();
        #pragma unroll
        for (int k = 0; k < BK; k++) {
            u64 b0 = *reinterpret_cast<const u64*>(&Bs[k][tx * 4]);
            u64 b1 = *reinterpret_cast<const u64*>(&Bs[k][tx * 4 + 2]);
            #pragma unroll
            for (int i = 0; i < 4; i++) {
                float a = As[k][ty * 4 + i];
                u64 ap = pack2(a, a);
                acc[i][0] = fma2(ap, b0, acc[i][0]);
                acc[i][1] = fma2(ap, b1, acc[i][1]);
            }
        }
        __syncthreads();
    }

    #pragma unroll
    for (int i = 0; i < 4; i++) {
        int m = m0 + ty * 4 + i;
        #pragma unroll
        for (int j = 0; j < 2; j++) {
            float lo, hi;
            unpack2(acc[i][j], lo, hi);
            int n = n0 + tx * 4 + j * 2;
            Cz[(size_t)m * N + n]     = lo;
            Cz[(size_t)m * N + n + 1] = hi;
        }
    }
}

__global__ void combine_tanh(const float* __restrict__ part, const float* __restrict__ bias,
                             float* __restrict__ C, int M, int N)
{
    int i = blockIdx.x * blockDim.x + threadIdx.x;
    if (i >= M * N) return;
    int n = i % N;
    C[i] = tanhf(part[i] + part[(size_t)M * N + i] + __ldg(bias + n));
}

// ---------------- small FC (fc3: 2048 -> 62) ----------------
__global__ void fc_small(const float* __restrict__ A, const float* __restrict__ W,
                         const float* __restrict__ bias, float* __restrict__ C,
                         int N, int K)
{
    int n = threadIdx.x;
    int m = blockIdx.x;
    if (n >= N) return;
    float acc = __ldg(bias + n);
    const float* a = A + (size_t)m * K;
    #pragma unroll 4
    for (int k = 0; k < K; k++)
        acc = fmaf(__ldg(a + k), __ldg(W + (size_t)k * N + n), acc);
    C[(size_t)m * N + n] = acc;
}

// ---------------- trajectory assembly ----------------
__global__ void traj_kernel(const float* __restrict__ p, const float* __restrict__ dict,
                            float* __restrict__ out)
{
    int b = blockIdx.x;
    __shared__ float sx[SSEG], sy[SSEG], s1[SSEG], s2[SSEG];
    __shared__ int sidx[SSEG];

    if (threadIdx.x == 0) {
        float cx = p[b * OUTDIM + 0];
        float cy = p[b * OUTDIM + 1];
        for (int s = 0; s < SSEG; s++) {
            float f0  = p[b * OUTDIM + 2 + s * 3 + 0];
            float sc1 = p[b * OUTDIM + 2 + s * 3 + 1];
            float sc2 = p[b * OUTDIM + 2 + s * 3 + 2];
            float r = rintf(f0);
            r = fminf(fmaxf(r, 0.0f), (float)(DDICT - 1));
            int id = (int)r;
            sidx[s] = id; s1[s] = sc1; s2[s] = sc2;
            sx[s] = cx; sy[s] = cy;
            cx += dict[((size_t)id * LSEG + (LSEG - 1)) * 2 + 0] * sc1;
            cy += dict[((size_t)id * LSEG + (LSEG - 1)) * 2 + 1] * sc2;
        }
    }
    __syncthreads();

    for (int i = threadIdx.x; i < SSEG * LSEG; i += blockDim.x) {
        int s = i / LSEG, l = i % LSEG;
        int id = sidx[s];
        float bx = dict[((size_t)id * LSEG + l) * 2 + 0];
        float by = dict[((size_t)id * LSEG + l) * 2 + 1];
        out[((size_t)b * SSEG * LSEG + i) * 2 + 0] = fmaf(bx, s1[s], sx[s]);
        out[((size_t)b * SSEG * LSEG + i) * 2 + 1] = fmaf(by, s2[s], sy[s]);
    }
}

// ---------------- launch ----------------
extern "C" void kernel_launch(void* const* d_in, const int* in_sizes, int n_in,
                              void* d_out, int out_size)
{
    const float* x   = (const float*)d_in[0];
    const float* w1  = (const float*)d_in[1];
    const float* b1  = (const float*)d_in[2];
    const float* w2  = (const float*)d_in[3];
    const float* b2  = (const float*)d_in[4];
    const float* w3  = (const float*)d_in[5];
    const float* b3  = (const float*)d_in[6];
    const float* w4  = (const float*)d_in[7];
    const float* b4  = (const float*)d_in[8];
    const float* fw1 = (const float*)d_in[9];
    const float* fb1 = (const float*)d_in[10];
    const float* fw2 = (const float*)d_in[11];
    const float* fb2 = (const float*)d_in[12];
    const float* fw3 = (const float*)d_in[13];
    const float* fb3 = (const float*)d_in[14];
    const float* dict= (const float*)d_in[15];
    float* out = (float*)d_out;

    uint32_t *h1p, *h2p, *h3p;
    float *h4, *a1, *a2, *pp, *part, *w1k;
    __half *w2h, *w2l, *w3h, *w3l, *w4h, *w4l;
    cudaGetSymbolAddress((void**)&h1p, g_h1p);
    cudaGetSymbolAddress((void**)&h2p, g_h2p);
    cudaGetSymbolAddress((void**)&h3p, g_h3p);
    cudaGetSymbolAddress((void**)&h4,  g_h4);
    cudaGetSymbolAddress((void**)&a1,  g_a1);
    cudaGetSymbolAddress((void**)&a2,  g_a2);
    cudaGetSymbolAddress((void**)&pp,  g_p);
    cudaGetSymbolAddress((void**)&part,g_part);
    cudaGetSymbolAddress((void**)&w1k, g_w1k);
    cudaGetSymbolAddress((void**)&w2h, g_w2h);
    cudaGetSymbolAddress((void**)&w2l, g_w2l);
    cudaGetSymbolAddress((void**)&w3h, g_w3h);
    cudaGetSymbolAddress((void**)&w3l, g_w3l);
    cudaGetSymbolAddress((void**)&w4h, g_w4h);
    cudaGetSymbolAddress((void**)&w4l, g_w4l);

    // dyn smem: max(4 half-tiles 40960 B, epilogue 128*132*4 = 67584 B)
    const int SMEM_DYN = 128 * 132 * 4;   // 67584
    cudaFuncSetAttribute((const void*)conv_mma<64,49,49,128,2,1>,
                         cudaFuncAttributeMaxDynamicSharedMemorySize, SMEM_DYN);
    cudaFuncSetAttribute((const void*)conv_mma<128,23,23,256,4,1>,
                         cudaFuncAttributeMaxDynamicSharedMemorySize, SMEM_DYN);
    cudaFuncSetAttribute((const void*)conv_mma<256,10,10,512,8,0>,
                         cudaFuncAttributeMaxDynamicSharedMemorySize, SMEM_DYN);

    // weight repacks
    repack_wk<<<(64*3*9 + 255) / 256, 256>>>(w1, w1k, 3, 64);
    repack_h2<<<(128*64*9  + 255) / 256, 256>>>(w2, w2h, w2l, 64,  128);
    repack_h2<<<(256*128*9 + 255) / 256, 256>>>(w3, w3h, w3l, 128, 256);
    repack_h2<<<(512*256*9 + 255) / 256, 256>>>(w4, w4h, w4l, 256, 512);

    // stage 1 (scalar FFMA2, packed output): (128,3,100,100) -> (128,64,49,49)
    {
        int total = NB * (64/8) * 49 * 49;
        conv_pool_relu2<3,100,100,49,49,64><<<(total + 255) / 256, 256>>>(x, w1k, b1, h1p);
    }
    // stage 2: -> (128,128,23,23) packed
    conv_mma<64,49,49,128,2,1><<<dim3(23, NB, 1), 256, SMEM_DYN>>>(h1p, w2h, w2l, b2, h2p);
    // stage 3: -> (128,256,10,10) packed
    conv_mma<128,23,23,256,4,1><<<dim3(5, NB, 2), 256, SMEM_DYN>>>(h2p, w3h, w3l, b3, h3p);
    // stage 4: -> (128,512,4,4) f32
    conv_mma<256,10,10,512,8,0><<<dim3(1, NB, 4), 256, SMEM_DYN>>>(h3p, w4h, w4l, b4, h4);

    // fc1: (128,8192) @ (8192,2048) + tanh, split-K=2
    {
        dim3 grid(2048 / 64, NB / 64, 2);
        gemm64_part<<<grid, 256>>>(h4, fw1, part, NB, 2048, 8192, 4096);
        combine_tanh<<<(NB * 2048 + 255) / 256, 256>>>(part, fb1, a1, NB, 2048);
    }
    // fc2: (128,2048) @ (2048,2048) + tanh
    {
        dim3 grid(2048 / 64, NB / 64);
        gemm64v2<1><<<grid, 256>>>(a1, fw2, fb2, a2, NB, 2048, 2048);
    }
    // fc3: (128,2048) @ (2048,62)
    fc_small<<<NB, 64>>>(a2, fw3, fb3, pp, OUTDIM, 2048);

    // trajectory assembly -> (128, 4000, 2)
    traj_kernel<<<NB, 256>>>(pp, dict, out);
}

// round 11
// speedup vs baseline: 1.1479x; 1.1479x over previous
#include <cuda_runtime.h>
#include <cuda_fp16.h>
#include <math.h>
#include <stdint.h>

typedef unsigned long long u64;

// ---------------- problem constants ----------------
#define NB   128
#define SSEG 20
#define DDICT 1000
#define LSEG 200
#define OUTDIM 62      // 2 + 3*20

// ---------------- f32x2 helpers ----------------
__device__ __forceinline__ u64 pack2(float a, float b) {
    u64 r; asm("mov.b64 %0, {%1, %2};" : "=l"(r) : "f"(a), "f"(b)); return r;
}
__device__ __forceinline__ u64 fma2(u64 a, u64 b, u64 c) {
    u64 d; asm("fma.rn.f32x2 %0, %1, %2, %3;" : "=l"(d) : "l"(a), "l"(b), "l"(c)); return d;
}
__device__ __forceinline__ void unpack2(u64 v, float& lo, float& hi) {
    asm("mov.b64 {%0, %1}, %2;" : "=f"(lo), "=f"(hi) : "l"(v));
}

// ---------------- fp16 mma helper: D += A(16x16) * B(16x8), f32 accum ----------------
__device__ __forceinline__ void mma16816(float* d, const uint32_t* a, const uint32_t* b) {
    asm volatile(
        "mma.sync.aligned.m16n8k16.row.col.f32.f16.f16.f32 "
        "{%0,%1,%2,%3}, {%4,%5,%6,%7}, {%8,%9}, {%0,%1,%2,%3};"
        : "+f"(d[0]), "+f"(d[1]), "+f"(d[2]), "+f"(d[3])
        : "r"(a[0]), "r"(a[1]), "r"(a[2]), "r"(a[3]), "r"(b[0]), "r"(b[1]));
}

// ---------------- scratch (device globals; conv inputs padded for shifted reads) --------
__device__ float g_h1[(size_t)NB*64*49*49 + 8192];
__device__ float g_h2[(size_t)NB*128*23*23 + 8192];
__device__ float g_h3[(size_t)NB*256*10*10 + 8192];
__device__ float g_h4[(size_t)NB*512*4*4];
__device__ float g_a1[NB*2048];
__device__ float g_a2[NB*2048];
__device__ float g_part[2*NB*2048];
__device__ float g_p [NB*OUTDIM];
__device__ float g_w1k[64*3*9];
// fp16-split weights: [kh][co][kw*CIN+ci], hi & lo halves
__device__ __align__(16) __half g_w2h[9*128*64],  g_w2l[9*128*64];
__device__ __align__(16) __half g_w3h[9*256*128], g_w3l[9*256*128];
__device__ __align__(16) __half g_w4h[9*512*256], g_w4l[9*512*256];

// ---------------- weight repack for scalar conv1 ----------------
__global__ void repack_wk(const float* __restrict__ w, float* __restrict__ wk, int CIN, int COUT)
{
    int i = blockIdx.x * blockDim.x + threadIdx.x;
    int total = COUT * CIN * 9;
    if (i >= total) return;
    int c  = i % 8;
    int k  = (i / 8) % 9;
    int ci = (i / 72) % CIN;
    int cg = i / (72 * CIN);
    wk[i] = w[((size_t)(cg * 8 + c) * CIN + ci) * 9 + k];
}

// ---------------- weight repack + fp16 split: -> [kh][co][kw*CIN+ci] ----------------
__global__ void repack_h2(const float* __restrict__ w, __half* __restrict__ whi,
                          __half* __restrict__ wlo, int CIN, int COUT)
{
    int i = blockIdx.x * blockDim.x + threadIdx.x;
    int tot = COUT * CIN * 9;
    if (i >= tot) return;
    int kw = i % 3, kh = (i / 3) % 3, ci = (i / 9) % CIN, co = i / (9 * CIN);
    float v = w[i];
    __half hi = __float2half_rn(v);
    __half lo = __float2half_rn(v - __half2float(hi));
    size_t d = (((size_t)kh * COUT + co) * 3 + kw) * CIN + ci;
    whi[d] = hi;
    wlo[d] = lo;
}

// ---------------- fp16-split mma.sync fused conv3x3 + bias + maxpool2 + relu ------------
// R8 kernel + register prefetch: LDGs for chunk s issue BEFORE the barrier, overlapping
// the previous chunk's MMA phase. Only STS sits between the barriers.
template<int CIN, int H, int W, int COUT, int ROWS>
__global__ __launch_bounds__(256, 2)
void conv_mma(const float* __restrict__ src, const __half* __restrict__ whi,
              const __half* __restrict__ wlo, const float* __restrict__ bias,
              float* __restrict__ dst)
{
    constexpr int HW  = H * W;
    constexpr int KCH = CIN / 32;
    constexpr int NCH = 9 * KCH;
    constexpr int PR  = ROWS / 2;
    constexpr int PWW = (W - 2) / 2;
    constexpr int PHH = (H - 2) / 2;
    constexpr int ST2 = 40;             // halves per smem tile row (32 k + 8 pad)
    constexpr int TILE = 128 * ST2;     // halves per tile
    constexpr int EST = 132;            // epilogue row stride (floats)

    extern __shared__ __align__(16) char smraw[];
    __half* Ah = (__half*)smraw;                 // [128][ST2]
    __half* Al = Ah + TILE;
    __half* Bh = Ah + 2 * TILE;
    __half* Bl = Ah + 3 * TILE;
    float*  eps = (float*)smraw;                 // epilogue overlay [128][EST]

    const int tid  = threadIdx.x;
    const int wid  = tid >> 5;
    const int lane = tid & 31;
    const int l4   = lane >> 2;
    const int lm   = lane & 3;

    const int img = blockIdx.y;
    const int r0  = blockIdx.x * ROWS;
    const int m0  = blockIdx.z * 128;
    const float* ib = src + (size_t)img * CIN * HW + r0 * W;

    const int co   = tid & 127;         // A fill row
    const int half = tid >> 7;          // k half (16 k each)
    const int bn   = tid & 127;         // B fill row (pixel)

    const int co0w = (wid >> 1) * 32;
    const int n0w  = (wid & 1) * 64;

    float acc[2][8][4];
    #pragma unroll
    for (int mb = 0; mb < 2; mb++)
        #pragma unroll
        for (int nb = 0; nb < 8; nb++)
            #pragma unroll
            for (int j = 0; j < 4; j++) acc[mb][nb][j] = 0.0f;

    for (int s = 0; s < NCH; s++) {
        int cc  = s % KCH;
        int kwv = (s / KCH) % 3;
        int khv = s / (3 * KCH);
        int ci0 = cc * 32;

        // ---- PREFETCH (before barrier): overlaps previous chunk's MMA phase ----
        size_t aoffg = (((size_t)khv * COUT + m0 + co) * 3 + kwv) * CIN + ci0 + half * 16;
        uint4 vh0 = *(const uint4*)(whi + aoffg);
        uint4 vh1 = *(const uint4*)(whi + aoffg + 8);
        uint4 vl0 = *(const uint4*)(wlo + aoffg);
        uint4 vl1 = *(const uint4*)(wlo + aoffg + 8);

        const float* bp = ib + bn + khv * W + kwv;
        float bx[16];
        #pragma unroll
        for (int i = 0; i < 16; i++)
            bx[i] = __ldg(bp + (size_t)(ci0 + half * 16 + i) * HW);

        if (s > 0) __syncthreads();     // everyone done reading previous tiles

        // ---- STS only between barriers ----
        {
            uint32_t sa = co * ST2 + half * 16;
            *(uint4*)(Ah + sa)     = vh0;
            *(uint4*)(Ah + sa + 8) = vh1;
            *(uint4*)(Al + sa)     = vl0;
            *(uint4*)(Al + sa + 8) = vl1;
        }
        {
            #pragma unroll
            for (int i = 0; i < 8; i++) {
                float x0 = bx[2 * i];
                float x1 = bx[2 * i + 1];
                __half h0 = __float2half_rn(x0);
                __half h1 = __float2half_rn(x1);
                __half l0 = __float2half_rn(x0 - __half2float(h0));
                __half l1 = __float2half_rn(x1 - __half2float(h1));
                uint32_t sa = bn * ST2 + half * 16 + 2 * i;
                *(__half2*)(Bh + sa) = __halves2half2(h0, h1);
                *(__half2*)(Bl + sa) = __halves2half2(l0, l1);
            }
        }
        __syncthreads();

        const uint32_t* Ah32 = (const uint32_t*)Ah;
        const uint32_t* Al32 = (const uint32_t*)Al;
        const uint32_t* Bh32 = (const uint32_t*)Bh;
        const uint32_t* Bl32 = (const uint32_t*)Bl;
        constexpr int SU = ST2 / 2;     // u32 (half2) per row = 20

        #pragma unroll
        for (int ks = 0; ks < 2; ks++) {
            int k0 = ks * 8;            // in half2 units
            uint32_t ah[2][4], al[2][4];
            #pragma unroll
            for (int mb = 0; mb < 2; mb++) {
                int m = co0w + mb * 16 + l4;
                ah[mb][0] = Ah32[m * SU + k0 + lm];
                ah[mb][1] = Ah32[(m + 8) * SU + k0 + lm];
                ah[mb][2] = Ah32[m * SU + k0 + lm + 4];
                ah[mb][3] = Ah32[(m + 8) * SU + k0 + lm + 4];
                al[mb][0] = Al32[m * SU + k0 + lm];
                al[mb][1] = Al32[(m + 8) * SU + k0 + lm];
                al[mb][2] = Al32[m * SU + k0 + lm + 4];
                al[mb][3] = Al32[(m + 8) * SU + k0 + lm + 4];
            }
            #pragma unroll
            for (int nb = 0; nb < 8; nb++) {
                int n = n0w + nb * 8 + l4;
                uint32_t bh[2], bl[2];
                bh[0] = Bh32[n * SU + k0 + lm];
                bh[1] = Bh32[n * SU + k0 + lm + 4];
                bl[0] = Bl32[n * SU + k0 + lm];
                bl[1] = Bl32[n * SU + k0 + lm + 4];
                #pragma unroll
                for (int mb = 0; mb < 2; mb++) {
                    mma16816(acc[mb][nb], ah[mb], bh);
                    mma16816(acc[mb][nb], ah[mb], bl);
                    mma16816(acc[mb][nb], al[mb], bh);
                }
            }
        }
    }

    __syncthreads();   // done with tiles; reuse smem for epilogue

    // ---- write accumulators to eps[co][pix] ----
    #pragma unroll
    for (int mb = 0; mb < 2; mb++) {
        #pragma unroll
        for (int nb = 0; nb < 8; nb++) {
            int n = n0w + nb * 8 + 2 * lm;
            int c_lo = co0w + mb * 16 + l4;
            *(float2*)&eps[c_lo * EST + n]       = make_float2(acc[mb][nb][0], acc[mb][nb][1]);
            *(float2*)&eps[(c_lo + 8) * EST + n] = make_float2(acc[mb][nb][2], acc[mb][nb][3]);
        }
    }
    __syncthreads();

    // ---- pool + bias + relu ----
    for (int t = tid; t < 128 * PR * PWW; t += 256) {
        int pw = t % PWW;
        int r  = t / PWW;
        int pr = r % PR;
        int c  = r / PR;
        int c0 = (2 * pr) * W + 2 * pw;
        const float* e = eps + c * EST;
        float v = fmaxf(fmaxf(e[c0], e[c0 + 1]), fmaxf(e[c0 + W], e[c0 + W + 1]))
                  + __ldg(bias + m0 + c);
        dst[(((size_t)img * COUT + m0 + c) * PHH + (r0 >> 1) + pr) * PWW + pw] = fmaxf(v, 0.0f);
    }
}

// ---------------- scalar conv stage 1 (CIN=3) — FFMA2 path ----------------
template<int CIN, int HIN, int WIN, int HP, int WP, int COUT>
__global__ __launch_bounds__(256)
void conv_pool_relu2(const float* __restrict__ in,
                     const float* __restrict__ wk,
                     const float* __restrict__ bias,
                     float* __restrict__ out)
{
    constexpr int COG = COUT / 8;
    int idx = blockIdx.x * blockDim.x + threadIdx.x;
    const int total = NB * COG * HP * WP;
    if (idx >= total) return;

    int pw = idx % WP;  int t = idx / WP;
    int ph = t % HP;    t /= HP;
    int cg = t % COG;   t /= COG;
    int b  = t;
    int co0 = cg * 8;

    u64 acc2[4][4];
    #pragma unroll
    for (int p = 0; p < 4; p++)
        #pragma unroll
        for (int j = 0; j < 4; j++) acc2[p][j] = 0ull;

    const float* inb = in + ((size_t)b * CIN * HIN + 2 * ph) * WIN + 2 * pw;
    const ulonglong2* __restrict__ wbase =
        reinterpret_cast<const ulonglong2*>(wk + (size_t)cg * CIN * 72);

    for (int ci = 0; ci < CIN; ci++) {
        const float* ip = inb + (size_t)ci * HIN * WIN;
        u64 xx[16];
        #pragma unroll
        for (int r = 0; r < 4; r++)
            #pragma unroll
            for (int c = 0; c < 4; c++) {
                float v = __ldg(ip + r * WIN + c);
                xx[r * 4 + c] = pack2(v, v);
            }
        const ulonglong2* wp = wbase + (size_t)ci * 18;
        #pragma unroll
        for (int k = 0; k < 9; k++) {
            ulonglong2 wA = wp[2 * k];
            ulonglong2 wB = wp[2 * k + 1];
            u64 wpair[4] = {wA.x, wA.y, wB.x, wB.y};
            int kh = k / 3, kw = k % 3;
            #pragma unroll
            for (int p = 0; p < 4; p++)
                #pragma unroll
                for (int dy = 0; dy < 2; dy++)
                    #pragma unroll
                    for (int dx = 0; dx < 2; dx++)
                        acc2[p][dy * 2 + dx] =
                            fma2(xx[(dy + kh) * 4 + dx + kw], wpair[p], acc2[p][dy * 2 + dx]);
        }
    }

    #pragma unroll
    for (int p = 0; p < 4; p++) {
        float l0, h0, l1, h1, l2, h2, l3, h3;
        unpack2(acc2[p][0], l0, h0);
        unpack2(acc2[p][1], l1, h1);
        unpack2(acc2[p][2], l2, h2);
        unpack2(acc2[p][3], l3, h3);
        float mlo = fmaxf(fmaxf(l0, l1), fmaxf(l2, l3)) + __ldg(bias + co0 + 2 * p);
        float mhi = fmaxf(fmaxf(h0, h1), fmaxf(h2, h3)) + __ldg(bias + co0 + 2 * p + 1);
        size_t o0 = (((size_t)b * COUT + co0 + 2 * p) * HP + ph) * WP + pw;
        out[o0]                   = fmaxf(mlo, 0.0f);
        out[o0 + (size_t)HP * WP] = fmaxf(mhi, 0.0f);
    }
}

// ---------------- FFMA2 tiled SGEMM ----------------
template<int ACT>
__global__ __launch_bounds__(256)
void gemm64v2(const float* __restrict__ A, const float* __restrict__ B,
              const float* __restrict__ bias, float* __restrict__ C,
              int M, int N, int K)
{
    const int BM = 64, BN = 64, BK = 16;
    __shared__ float As[BK][BM + 1];
    __shared__ float Bs[BK][BN];
    int tx = threadIdx.x % 16, ty = threadIdx.x / 16;
    int m0 = blockIdx.y * BM, n0 = blockIdx.x * BN;

    u64 acc[4][2] = {};
    for (int kk = 0; kk < K; kk += BK) {
        #pragma unroll
        for (int i = 0; i < 4; i++) {
            int l = threadIdx.x + i * 256;
            int m = l / 16, k = l % 16;
            As[k][m] = A[(size_t)(m0 + m) * K + kk + k];
        }
        #pragma unroll
        for (int i = 0; i < 4; i++) {
            int l = threadIdx.x + i * 256;
            int n = l % 64, k = l / 64;
            Bs[k][n] = B[(size_t)(kk + k) * N + n0 + n];
        }
        __syncthreads();
        #pragma unroll
        for (int k = 0; k < BK; k++) {
            u64 b0 = *reinterpret_cast<const u64*>(&Bs[k][tx * 4]);
            u64 b1 = *reinterpret_cast<const u64*>(&Bs[k][tx * 4 + 2]);
            #pragma unroll
            for (int i = 0; i < 4; i++) {
                float a = As[k][ty * 4 + i];
                u64 ap = pack2(a, a);
                acc[i][0] = fma2(ap, b0, acc[i][0]);
                acc[i][1] = fma2(ap, b1, acc[i][1]);
            }
        }
        __syncthreads();
    }

    #pragma unroll
    for (int i = 0; i < 4; i++) {
        int m = m0 + ty * 4 + i;
        #pragma unroll
        for (int j = 0; j < 2; j++) {
            float lo, hi;
            unpack2(acc[i][j], lo, hi);
            int n = n0 + tx * 4 + j * 2;
            float v0 = lo + __ldg(bias + n);
            float v1 = hi + __ldg(bias + n + 1);
            if (ACT == 1) { v0 = tanhf(v0); v1 = tanhf(v1); }
            C[(size_t)m * N + n]     = v0;
            C[(size_t)m * N + n + 1] = v1;
        }
    }
}

// ---------------- split-K partial GEMM ----------------
__global__ __launch_bounds__(256)
void gemm64_part(const float* __restrict__ A, const float* __restrict__ B,
                 float* __restrict__ Cpart, int M, int N, int K, int Ks)
{
    const int BM = 64, BN = 64, BK = 16;
    __shared__ float As[BK][BM + 1];
    __shared__ float Bs[BK][BN];
    int tx = threadIdx.x % 16, ty = threadIdx.x / 16;
    int m0 = blockIdx.y * BM, n0 = blockIdx.x * BN;
    int z = blockIdx.z;
    int k0 = z * Ks;
    float* Cz = Cpart + (size_t)z * M * N;

    u64 acc[4][2] = {};
    for (int kk = k0; kk < k0 + Ks; kk += BK) {
        #pragma unroll
        for (int i = 0; i < 4; i++) {
            int l = threadIdx.x + i * 256;
            int m = l / 16, k = l % 16;
            As[k][m] = A[(size_t)(m0 + m) * K + kk + k];
        }
        #pragma unroll
        for (int i = 0; i < 4; i++) {
            int l = threadIdx.x + i * 256;
            int n = l % 64, k = l / 64;
            Bs[k][n] = B[(size_t)(kk + k) * N + n0 + n];
        }
        __syncthreads();
        #pragma unroll
        for (int k = 0; k < BK; k++) {
            u64 b0 = *reinterpret_cast<const u64*>(&Bs[k][tx * 4]);
            u64 b1 = *reinterpret_cast<const u64*>(&Bs[k][tx * 4 + 2]);
            #pragma unroll
            for (int i = 0; i < 4; i++) {
                float a = As[k][ty * 4 + i];
                u64 ap = pack2(a, a);
                acc[i][0] = fma2(ap, b0, acc[i][0]);
                acc[i][1] = fma2(ap, b1, acc[i][1]);
            }
        }
        __syncthreads();
    }

    #pragma unroll
    for (int i = 0; i < 4; i++) {
        int m = m0 + ty * 4 + i;
        #pragma unroll
        for (int j = 0; j < 2; j++) {
            float lo, hi;
            unpack2(acc[i][j], lo, hi);
            int n = n0 + tx * 4 + j * 2;
            Cz[(size_t)m * N + n]     = lo;
            Cz[(size_t)m * N + n + 1] = hi;
        }
    }
}

__global__ void combine_tanh(const float* __restrict__ part, const float* __restrict__ bias,
                             float* __restrict__ C, int M, int N)
{
    int i = blockIdx.x * blockDim.x + threadIdx.x;
    if (i >= M * N) return;
    int n = i % N;
    C[i] = tanhf(part[i] + part[(size_t)M * N + i] + __ldg(bias + n));
}

// ---------------- small FC (fc3: 2048 -> 62), k-split x4 ----------------
__global__ void fc_small(const float* __restrict__ A, const float* __restrict__ W,
                         const float* __restrict__ bias, float* __restrict__ C,
                         int N, int K)
{
    __shared__ float red[4][64];
    int t  = threadIdx.x;        // 256
    int n  = t & 63;
    int sl = t >> 6;             // 0..3
    int m  = blockIdx.x;
    int Ks = K / 4;

    float acc = 0.0f;
    if (n < N) {
        const float* a = A + (size_t)m * K + sl * Ks;
        const float* w = W + (size_t)sl * Ks * N + n;
        #pragma unroll 4
        for (int k = 0; k < Ks; k++)
            acc = fmaf(__ldg(a + k), __ldg(w + (size_t)k * N), acc);
    }
    red[sl][n] = acc;
    __syncthreads();
    if (sl == 0 && n < N) {
        C[(size_t)m * N + n] = red[0][n] + red[1][n] + red[2][n] + red[3][n]
                               + __ldg(bias + n);
    }
}

// ---------------- trajectory assembly ----------------
__global__ void traj_kernel(const float* __restrict__ p, const float* __restrict__ dict,
                            float* __restrict__ out)
{
    int b = blockIdx.x;
    __shared__ float sx[SSEG], sy[SSEG], s1[SSEG], s2[SSEG];
    __shared__ int sidx[SSEG];

    if (threadIdx.x == 0) {
        float cx = p[b * OUTDIM + 0];
        float cy = p[b * OUTDIM + 1];
        for (int s = 0; s < SSEG; s++) {
            float f0  = p[b * OUTDIM + 2 + s * 3 + 0];
            float sc1 = p[b * OUTDIM + 2 + s * 3 + 1];
            float sc2 = p[b * OUTDIM + 2 + s * 3 + 2];
            float r = rintf(f0);
            r = fminf(fmaxf(r, 0.0f), (float)(DDICT - 1));
            int id = (int)r;
            sidx[s] = id; s1[s] = sc1; s2[s] = sc2;
            sx[s] = cx; sy[s] = cy;
            cx += dict[((size_t)id * LSEG + (LSEG - 1)) * 2 + 0] * sc1;
            cy += dict[((size_t)id * LSEG + (LSEG - 1)) * 2 + 1] * sc2;
        }
    }
    __syncthreads();

    for (int i = threadIdx.x; i < SSEG * LSEG; i += blockDim.x) {
        int s = i / LSEG, l = i % LSEG;
        int id = sidx[s];
        float bx = dict[((size_t)id * LSEG + l) * 2 + 0];
        float by = dict[((size_t)id * LSEG + l) * 2 + 1];
        out[((size_t)b * SSEG * LSEG + i) * 2 + 0] = fmaf(bx, s1[s], sx[s]);
        out[((size_t)b * SSEG * LSEG + i) * 2 + 1] = fmaf(by, s2[s], sy[s]);
    }
}

// ---------------- launch ----------------
extern "C" void kernel_launch(void* const* d_in, const int* in_sizes, int n_in,
                              void* d_out, int out_size)
{
    const float* x   = (const float*)d_in[0];
    const float* w1  = (const float*)d_in[1];
    const float* b1  = (const float*)d_in[2];
    const float* w2  = (const float*)d_in[3];
    const float* b2  = (const float*)d_in[4];
    const float* w3  = (const float*)d_in[5];
    const float* b3  = (const float*)d_in[6];
    const float* w4  = (const float*)d_in[7];
    const float* b4  = (const float*)d_in[8];
    const float* fw1 = (const float*)d_in[9];
    const float* fb1 = (const float*)d_in[10];
    const float* fw2 = (const float*)d_in[11];
    const float* fb2 = (const float*)d_in[12];
    const float* fw3 = (const float*)d_in[13];
    const float* fb3 = (const float*)d_in[14];
    const float* dict= (const float*)d_in[15];
    float* out = (float*)d_out;

    float *h1, *h2, *h3, *h4, *a1, *a2, *pp, *part, *w1k;
    __half *w2h, *w2l, *w3h, *w3l, *w4h, *w4l;
    cudaGetSymbolAddress((void**)&h1,  g_h1);
    cudaGetSymbolAddress((void**)&h2,  g_h2);
    cudaGetSymbolAddress((void**)&h3,  g_h3);
    cudaGetSymbolAddress((void**)&h4,  g_h4);
    cudaGetSymbolAddress((void**)&a1,  g_a1);
    cudaGetSymbolAddress((void**)&a2,  g_a2);
    cudaGetSymbolAddress((void**)&pp,  g_p);
    cudaGetSymbolAddress((void**)&part,g_part);
    cudaGetSymbolAddress((void**)&w1k, g_w1k);
    cudaGetSymbolAddress((void**)&w2h, g_w2h);
    cudaGetSymbolAddress((void**)&w2l, g_w2l);
    cudaGetSymbolAddress((void**)&w3h, g_w3h);
    cudaGetSymbolAddress((void**)&w3l, g_w3l);
    cudaGetSymbolAddress((void**)&w4h, g_w4h);
    cudaGetSymbolAddress((void**)&w4l, g_w4l);

    // dyn smem: max(4 half-tiles 40960 B, epilogue 128*132*4 = 67584 B)
    const int SMEM_DYN = 128 * 132 * 4;   // 67584
    cudaFuncSetAttribute((const void*)conv_mma<64,49,49,128,2>,
                         cudaFuncAttributeMaxDynamicSharedMemorySize, SMEM_DYN);
    cudaFuncSetAttribute((const void*)conv_mma<128,23,23,256,4>,
                         cudaFuncAttributeMaxDynamicSharedMemorySize, SMEM_DYN);
    cudaFuncSetAttribute((const void*)conv_mma<256,10,10,512,8>,
                         cudaFuncAttributeMaxDynamicSharedMemorySize, SMEM_DYN);

    // weight repacks
    repack_wk<<<(64*3*9 + 255) / 256, 256>>>(w1, w1k, 3, 64);
    repack_h2<<<(128*64*9  + 255) / 256, 256>>>(w2, w2h, w2l, 64,  128);
    repack_h2<<<(256*128*9 + 255) / 256, 256>>>(w3, w3h, w3l, 128, 256);
    repack_h2<<<(512*256*9 + 255) / 256, 256>>>(w4, w4h, w4l, 256, 512);

    // stage 1 (scalar FFMA2): (128,3,100,100) -> (128,64,49,49)
    {
        int total = NB * (64/8) * 49 * 49;
        conv_pool_relu2<3,100,100,49,49,64><<<(total + 255) / 256, 256>>>(x, w1k, b1, h1);
    }
    // stage 2 (fp16-split mma): -> (128,128,23,23)
    conv_mma<64,49,49,128,2><<<dim3(23, NB, 1), 256, SMEM_DYN>>>(h1, w2h, w2l, b2, h2);
    // stage 3: -> (128,256,10,10)
    conv_mma<128,23,23,256,4><<<dim3(5, NB, 2), 256, SMEM_DYN>>>(h2, w3h, w3l, b3, h3);
    // stage 4: -> (128,512,4,4)
    conv_mma<256,10,10,512,8><<<dim3(1, NB, 4), 256, SMEM_DYN>>>(h3, w4h, w4l, b4, h4);

    // fc1: (128,8192) @ (8192,2048) + tanh, split-K=2
    {
        dim3 grid(2048 / 64, NB / 64, 2);
        gemm64_part<<<grid, 256>>>(h4, fw1, part, NB, 2048, 8192, 4096);
        combine_tanh<<<(NB * 2048 + 255) / 256, 256>>>(part, fb1, a1, NB, 2048);
    }
    // fc2: (128,2048) @ (2048,2048) + tanh
    {
        dim3 grid(2048 / 64, NB / 64);
        gemm64v2<1><<<grid, 256>>>(a1, fw2, fb2, a2, NB, 2048, 2048);
    }
    // fc3: (128,2048) @ (2048,62)
    fc_small<<<NB, 256>>>(a2, fw3, fb3, pp, OUTDIM, 2048);

    // trajectory assembly -> (128, 4000, 2)
    traj_kernel<<<NB, 256>>>(pp, dict, out);
}

// round 12
// speedup vs baseline: 1.2169x; 1.0601x over previous
#include <cuda_runtime.h>
#include <cuda_fp16.h>
#include <math.h>
#include <stdint.h>

typedef unsigned long long u64;

// ---------------- problem constants ----------------
#define NB   128
#define SSEG 20
#define DDICT 1000
#define LSEG 200
#define OUTDIM 62      // 2 + 3*20

// ---------------- f32x2 helpers ----------------
__device__ __forceinline__ u64 pack2(float a, float b) {
    u64 r; asm("mov.b64 %0, {%1, %2};" : "=l"(r) : "f"(a), "f"(b)); return r;
}
__device__ __forceinline__ u64 fma2(u64 a, u64 b, u64 c) {
    u64 d; asm("fma.rn.f32x2 %0, %1, %2, %3;" : "=l"(d) : "l"(a), "l"(b), "l"(c)); return d;
}
__device__ __forceinline__ void unpack2(u64 v, float& lo, float& hi) {
    asm("mov.b64 {%0, %1}, %2;" : "=f"(lo), "=f"(hi) : "l"(v));
}

// ---------------- fp16 mma helper: D += A(16x16) * B(16x8), f32 accum ----------------
__device__ __forceinline__ void mma16816(float* d, const uint32_t* a, const uint32_t* b) {
    asm volatile(
        "mma.sync.aligned.m16n8k16.row.col.f32.f16.f16.f32 "
        "{%0,%1,%2,%3}, {%4,%5,%6,%7}, {%8,%9}, {%0,%1,%2,%3};"
        : "+f"(d[0]), "+f"(d[1]), "+f"(d[2]), "+f"(d[3])
        : "r"(a[0]), "r"(a[1]), "r"(a[2]), "r"(a[3]), "r"(b[0]), "r"(b[1]));
}

// ---------------- scratch (device globals; conv inputs padded for shifted reads) --------
__device__ float g_h1[(size_t)NB*64*49*49 + 8192];
__device__ float g_h2[(size_t)NB*128*23*23 + 8192];
__device__ float g_h3[(size_t)NB*256*10*10 + 8192];
__device__ float g_h4[(size_t)NB*512*4*4];
__device__ float g_a1[NB*2048];
__device__ float g_a2[NB*2048];
__device__ float g_part[2*NB*2048];
__device__ float g_p [NB*OUTDIM];
__device__ float g_w1k[64*3*9];
// fp16-split weights: [kh][co][kw*CIN+ci], hi & lo halves
__device__ __align__(16) __half g_w2h[9*128*64],  g_w2l[9*128*64];
__device__ __align__(16) __half g_w3h[9*256*128], g_w3l[9*256*128];
__device__ __align__(16) __half g_w4h[9*512*256], g_w4l[9*512*256];

// ---------------- weight repack for scalar conv1 ----------------
__global__ void repack_wk(const float* __restrict__ w, float* __restrict__ wk, int CIN, int COUT)
{
    int i = blockIdx.x * blockDim.x + threadIdx.x;
    int total = COUT * CIN * 9;
    if (i >= total) return;
    int c  = i % 8;
    int k  = (i / 8) % 9;
    int ci = (i / 72) % CIN;
    int cg = i / (72 * CIN);
    wk[i] = w[((size_t)(cg * 8 + c) * CIN + ci) * 9 + k];
}

// ---------------- weight repack + fp16 split: -> [kh][co][kw*CIN+ci] ----------------
__global__ void repack_h2(const float* __restrict__ w, __half* __restrict__ whi,
                          __half* __restrict__ wlo, int CIN, int COUT)
{
    int i = blockIdx.x * blockDim.x + threadIdx.x;
    int tot = COUT * CIN * 9;
    if (i >= tot) return;
    int kw = i % 3, kh = (i / 3) % 3, ci = (i / 9) % CIN, co = i / (9 * CIN);
    float v = w[i];
    __half hi = __float2half_rn(v);
    __half lo = __float2half_rn(v - __half2float(hi));
    size_t d = (((size_t)kh * COUT + co) * 3 + kw) * CIN + ci;
    whi[d] = hi;
    wlo[d] = lo;
}

// ---------------- fp16-split mma.sync fused conv3x3 + bias + maxpool2 + relu ------------
// Double-buffered SMEM tiles: per iteration prefetch(s+1 LDG) -> MMA(buf[s&1]) ->
// STS(s+1 -> buf[(s+1)&1]) -> one __syncthreads. STS overlaps MMA issue.
template<int CIN, int H, int W, int COUT, int ROWS>
__global__ __launch_bounds__(256, 2)
void conv_mma(const float* __restrict__ src, const __half* __restrict__ whi,
              const __half* __restrict__ wlo, const float* __restrict__ bias,
              float* __restrict__ dst)
{
    constexpr int HW  = H * W;
    constexpr int KCH = CIN / 32;
    constexpr int NCH = 9 * KCH;
    constexpr int PR  = ROWS / 2;
    constexpr int PWW = (W - 2) / 2;
    constexpr int PHH = (H - 2) / 2;
    constexpr int ST2 = 40;                 // halves per smem tile row (32 k + 8 pad)
    constexpr int TILE = 128 * ST2;         // halves per tile
    constexpr int TB   = TILE * 2;          // bytes per tile
    constexpr int EST = 132;                // epilogue row stride (floats)

    extern __shared__ __align__(16) char smraw[];
    float* eps = (float*)smraw;             // epilogue overlay [128][EST]

    const int tid  = threadIdx.x;
    const int wid  = tid >> 5;
    const int lane = tid & 31;
    const int l4   = lane >> 2;
    const int lm   = lane & 3;

    const int img = blockIdx.y;
    const int r0  = blockIdx.x * ROWS;
    const int m0  = blockIdx.z * 128;
    const float* ib = src + (size_t)img * CIN * HW + r0 * W;

    const int co   = tid & 127;             // A fill row
    const int half = tid >> 7;              // k half (16 k each)
    const int bn   = tid & 127;             // B fill row (pixel)

    const int co0w = (wid >> 1) * 32;
    const int n0w  = (wid & 1) * 64;

    float acc[2][8][4];
    #pragma unroll
    for (int mb = 0; mb < 2; mb++)
        #pragma unroll
        for (int nb = 0; nb < 8; nb++)
            #pragma unroll
            for (int j = 0; j < 4; j++) acc[mb][nb][j] = 0.0f;

    uint4 vh0, vh1, vl0, vl1;
    float bx[16];

    // ---- prefetch + fill chunk 0 into buffer 0 ----
    {
        size_t aoffg = (((size_t)0 * COUT + m0 + co) * 3 + 0) * CIN + 0 + half * 16;
        vh0 = *(const uint4*)(whi + aoffg);
        vh1 = *(const uint4*)(whi + aoffg + 8);
        vl0 = *(const uint4*)(wlo + aoffg);
        vl1 = *(const uint4*)(wlo + aoffg + 8);
        const float* bp = ib + bn;
        #pragma unroll
        for (int i = 0; i < 16; i++)
            bx[i] = __ldg(bp + (size_t)(half * 16 + i) * HW);

        __half* Ah = (__half*)(smraw);
        __half* Al = (__half*)(smraw + TB);
        __half* Bh = (__half*)(smraw + 2 * TB);
        __half* Bl = (__half*)(smraw + 3 * TB);
        uint32_t sa = co * ST2 + half * 16;
        *(uint4*)(Ah + sa)     = vh0;
        *(uint4*)(Ah + sa + 8) = vh1;
        *(uint4*)(Al + sa)     = vl0;
        *(uint4*)(Al + sa + 8) = vl1;
        #pragma unroll
        for (int i = 0; i < 8; i++) {
            float x0 = bx[2 * i], x1 = bx[2 * i + 1];
            __half h0 = __float2half_rn(x0);
            __half h1 = __float2half_rn(x1);
            __half l0 = __float2half_rn(x0 - __half2float(h0));
            __half l1 = __float2half_rn(x1 - __half2float(h1));
            uint32_t sb = bn * ST2 + half * 16 + 2 * i;
            *(__half2*)(Bh + sb) = __halves2half2(h0, h1);
            *(__half2*)(Bl + sb) = __halves2half2(l0, l1);
        }
    }
    __syncthreads();

    for (int s = 0; s < NCH; s++) {
        int cur = s & 1;

        // ---- prefetch chunk s+1 (LDG latency covered by MMA phase) ----
        if (s + 1 < NCH) {
            int sn  = s + 1;
            int cc  = sn % KCH;
            int kwv = (sn / KCH) % 3;
            int khv = sn / (3 * KCH);
            int ci0 = cc * 32;
            size_t aoffg = (((size_t)khv * COUT + m0 + co) * 3 + kwv) * CIN + ci0 + half * 16;
            vh0 = *(const uint4*)(whi + aoffg);
            vh1 = *(const uint4*)(whi + aoffg + 8);
            vl0 = *(const uint4*)(wlo + aoffg);
            vl1 = *(const uint4*)(wlo + aoffg + 8);
            const float* bp = ib + bn + khv * W + kwv;
            #pragma unroll
            for (int i = 0; i < 16; i++)
                bx[i] = __ldg(bp + (size_t)(ci0 + half * 16 + i) * HW);
        }

        // ---- MMA phase on buffer cur ----
        {
            const uint32_t* Ah32 = (const uint32_t*)(smraw + cur * 4 * TB);
            const uint32_t* Al32 = (const uint32_t*)(smraw + cur * 4 * TB + TB);
            const uint32_t* Bh32 = (const uint32_t*)(smraw + cur * 4 * TB + 2 * TB);
            const uint32_t* Bl32 = (const uint32_t*)(smraw + cur * 4 * TB + 3 * TB);
            constexpr int SU = ST2 / 2;     // u32 (half2) per row = 20

            #pragma unroll
            for (int ks = 0; ks < 2; ks++) {
                int k0 = ks * 8;            // in half2 units
                uint32_t ah[2][4], al[2][4];
                #pragma unroll
                for (int mb = 0; mb < 2; mb++) {
                    int m = co0w + mb * 16 + l4;
                    ah[mb][0] = Ah32[m * SU + k0 + lm];
                    ah[mb][1] = Ah32[(m + 8) * SU + k0 + lm];
                    ah[mb][2] = Ah32[m * SU + k0 + lm + 4];
                    ah[mb][3] = Ah32[(m + 8) * SU + k0 + lm + 4];
                    al[mb][0] = Al32[m * SU + k0 + lm];
                    al[mb][1] = Al32[(m + 8) * SU + k0 + lm];
                    al[mb][2] = Al32[m * SU + k0 + lm + 4];
                    al[mb][3] = Al32[(m + 8) * SU + k0 + lm + 4];
                }
                #pragma unroll
                for (int nb = 0; nb < 8; nb++) {
                    int n = n0w + nb * 8 + l4;
                    uint32_t bh[2], bl[2];
                    bh[0] = Bh32[n * SU + k0 + lm];
                    bh[1] = Bh32[n * SU + k0 + lm + 4];
                    bl[0] = Bl32[n * SU + k0 + lm];
                    bl[1] = Bl32[n * SU + k0 + lm + 4];
                    #pragma unroll
                    for (int mb = 0; mb < 2; mb++) {
                        mma16816(acc[mb][nb], ah[mb], bh);
                        mma16816(acc[mb][nb], ah[mb], bl);
                        mma16816(acc[mb][nb], al[mb], bh);
                    }
                }
            }
        }

        // ---- STS chunk s+1 into the other buffer (overlaps MMA issue) ----
        if (s + 1 < NCH) {
            int nb2 = (s + 1) & 1;
            __half* Ah = (__half*)(smraw + nb2 * 4 * TB);
            __half* Al = (__half*)(smraw + nb2 * 4 * TB + TB);
            __half* Bh = (__half*)(smraw + nb2 * 4 * TB + 2 * TB);
            __half* Bl = (__half*)(smraw + nb2 * 4 * TB + 3 * TB);
            uint32_t sa = co * ST2 + half * 16;
            *(uint4*)(Ah + sa)     = vh0;
            *(uint4*)(Ah + sa + 8) = vh1;
            *(uint4*)(Al + sa)     = vl0;
            *(uint4*)(Al + sa + 8) = vl1;
            #pragma unroll
            for (int i = 0; i < 8; i++) {
                float x0 = bx[2 * i], x1 = bx[2 * i + 1];
                __half h0 = __float2half_rn(x0);
                __half h1 = __float2half_rn(x1);
                __half l0 = __float2half_rn(x0 - __half2float(h0));
                __half l1 = __float2half_rn(x1 - __half2float(h1));
                uint32_t sb = bn * ST2 + half * 16 + 2 * i;
                *(__half2*)(Bh + sb) = __halves2half2(h0, h1);
                *(__half2*)(Bl + sb) = __halves2half2(l0, l1);
            }
        }
        __syncthreads();
    }

    // ---- write accumulators to eps[co][pix] ----
    #pragma unroll
    for (int mb = 0; mb < 2; mb++) {
        #pragma unroll
        for (int nb = 0; nb < 8; nb++) {
            int n = n0w + nb * 8 + 2 * lm;
            int c_lo = co0w + mb * 16 + l4;
            *(float2*)&eps[c_lo * EST + n]       = make_float2(acc[mb][nb][0], acc[mb][nb][1]);
            *(float2*)&eps[(c_lo + 8) * EST + n] = make_float2(acc[mb][nb][2], acc[mb][nb][3]);
        }
    }
    __syncthreads();

    // ---- pool + bias + relu ----
    for (int t = tid; t < 128 * PR * PWW; t += 256) {
        int pw = t % PWW;
        int r  = t / PWW;
        int pr = r % PR;
        int c  = r / PR;
        int c0 = (2 * pr) * W + 2 * pw;
        const float* e = eps + c * EST;
        float v = fmaxf(fmaxf(e[c0], e[c0 + 1]), fmaxf(e[c0 + W], e[c0 + W + 1]))
                  + __ldg(bias + m0 + c);
        dst[(((size_t)img * COUT + m0 + c) * PHH + (r0 >> 1) + pr) * PWW + pw] = fmaxf(v, 0.0f);
    }
}

// ---------------- scalar conv stage 1 (CIN=3) — FFMA2 path ----------------
template<int CIN, int HIN, int WIN, int HP, int WP, int COUT>
__global__ __launch_bounds__(256)
void conv_pool_relu2(const float* __restrict__ in,
                     const float* __restrict__ wk,
                     const float* __restrict__ bias,
                     float* __restrict__ out)
{
    constexpr int COG = COUT / 8;
    int idx = blockIdx.x * blockDim.x + threadIdx.x;
    const int total = NB * COG * HP * WP;
    if (idx >= total) return;

    int pw = idx % WP;  int t = idx / WP;
    int ph = t % HP;    t /= HP;
    int cg = t % COG;   t /= COG;
    int b  = t;
    int co0 = cg * 8;

    u64 acc2[4][4];
    #pragma unroll
    for (int p = 0; p < 4; p++)
        #pragma unroll
        for (int j = 0; j < 4; j++) acc2[p][j] = 0ull;

    const float* inb = in + ((size_t)b * CIN * HIN + 2 * ph) * WIN + 2 * pw;
    const ulonglong2* __restrict__ wbase =
        reinterpret_cast<const ulonglong2*>(wk + (size_t)cg * CIN * 72);

    for (int ci = 0; ci < CIN; ci++) {
        const float* ip = inb + (size_t)ci * HIN * WIN;
        u64 xx[16];
        #pragma unroll
        for (int r = 0; r < 4; r++)
            #pragma unroll
            for (int c = 0; c < 4; c++) {
                float v = __ldg(ip + r * WIN + c);
                xx[r * 4 + c] = pack2(v, v);
            }
        const ulonglong2* wp = wbase + (size_t)ci * 18;
        #pragma unroll
        for (int k = 0; k < 9; k++) {
            ulonglong2 wA = wp[2 * k];
            ulonglong2 wB = wp[2 * k + 1];
            u64 wpair[4] = {wA.x, wA.y, wB.x, wB.y};
            int kh = k / 3, kw = k % 3;
            #pragma unroll
            for (int p = 0; p < 4; p++)
                #pragma unroll
                for (int dy = 0; dy < 2; dy++)
                    #pragma unroll
                    for (int dx = 0; dx < 2; dx++)
                        acc2[p][dy * 2 + dx] =
                            fma2(xx[(dy + kh) * 4 + dx + kw], wpair[p], acc2[p][dy * 2 + dx]);
        }
    }

    #pragma unroll
    for (int p = 0; p < 4; p++) {
        float l0, h0, l1, h1, l2, h2, l3, h3;
        unpack2(acc2[p][0], l0, h0);
        unpack2(acc2[p][1], l1, h1);
        unpack2(acc2[p][2], l2, h2);
        unpack2(acc2[p][3], l3, h3);
        float mlo = fmaxf(fmaxf(l0, l1), fmaxf(l2, l3)) + __ldg(bias + co0 + 2 * p);
        float mhi = fmaxf(fmaxf(h0, h1), fmaxf(h2, h3)) + __ldg(bias + co0 + 2 * p + 1);
        size_t o0 = (((size_t)b * COUT + co0 + 2 * p) * HP + ph) * WP + pw;
        out[o0]                   = fmaxf(mlo, 0.0f);
        out[o0 + (size_t)HP * WP] = fmaxf(mhi, 0.0f);
    }
}

// ---------------- split-K partial GEMM (FFMA2) ----------------
__global__ __launch_bounds__(256)
void gemm64_part(const float* __restrict__ A, const float* __restrict__ B,
                 float* __restrict__ Cpart, int M, int N, int K, int Ks)
{
    const int BM = 64, BN = 64, BK = 16;
    __shared__ float As[BK][BM + 1];
    __shared__ float Bs[BK][BN];
    int tx = threadIdx.x % 16, ty = threadIdx.x / 16;
    int m0 = blockIdx.y * BM, n0 = blockIdx.x * BN;
    int z = blockIdx.z;
    int k0 = z * Ks;
    float* Cz = Cpart + (size_t)z * M * N;

    u64 acc[4][2] = {};
    for (int kk = k0; kk < k0 + Ks; kk += BK) {
        #pragma unroll
        for (int i = 0; i < 4; i++) {
            int l = threadIdx.x + i * 256;
            int m = l / 16, k = l % 16;
            As[k][m] = A[(size_t)(m0 + m) * K + kk + k];
        }
        #pragma unroll
        for (int i = 0; i < 4; i++) {
            int l = threadIdx.x + i * 256;
            int n = l % 64, k = l / 64;
            Bs[k][n] = B[(size_t)(kk + k) * N + n0 + n];
        }
        __syncthreads();
        #pragma unroll
        for (int k = 0; k < BK; k++) {
            u64 b0 = *reinterpret_cast<const u64*>(&Bs[k][tx * 4]);
            u64 b1 = *reinterpret_cast<const u64*>(&Bs[k][tx * 4 + 2]);
            #pragma unroll
            for (int i = 0; i < 4; i++) {
                float a = As[k][ty * 4 + i];
                u64 ap = pack2(a, a);
                acc[i][0] = fma2(ap, b0, acc[i][0]);
                acc[i][1] = fma2(ap, b1, acc[i][1]);
            }
        }
        __syncthreads();
    }

    #pragma unroll
    for (int i = 0; i < 4; i++) {
        int m = m0 + ty * 4 + i;
        #pragma unroll
        for (int j = 0; j < 2; j++) {
            float lo, hi;
            unpack2(acc[i][j], lo, hi);
            int n = n0 + tx * 4 + j * 2;
            Cz[(size_t)m * N + n]     = lo;
            Cz[(size_t)m * N + n + 1] = hi;
        }
    }
}

__global__ void combine_tanh(const float* __restrict__ part, const float* __restrict__ bias,
                             float* __restrict__ C, int M, int N)
{
    int i = blockIdx.x * blockDim.x + threadIdx.x;
    if (i >= M * N) return;
    int n = i % N;
    C[i] = tanhf(part[i] + part[(size_t)M * N + i] + __ldg(bias + n));
}

// ---------------- small FC (fc3: 2048 -> 62), k-split x4 ----------------
__global__ void fc_small(const float* __restrict__ A, const float* __restrict__ W,
                         const float* __restrict__ bias, float* __restrict__ C,
                         int N, int K)
{
    __shared__ float red[4][64];
    int t  = threadIdx.x;        // 256
    int n  = t & 63;
    int sl = t >> 6;             // 0..3
    int m  = blockIdx.x;
    int Ks = K / 4;

    float acc = 0.0f;
    if (n < N) {
        const float* a = A + (size_t)m * K + sl * Ks;
        const float* w = W + (size_t)sl * Ks * N + n;
        #pragma unroll 4
        for (int k = 0; k < Ks; k++)
            acc = fmaf(__ldg(a + k), __ldg(w + (size_t)k * N), acc);
    }
    red[sl][n] = acc;
    __syncthreads();
    if (sl == 0 && n < N) {
        C[(size_t)m * N + n] = red[0][n] + red[1][n] + red[2][n] + red[3][n]
                               + __ldg(bias + n);
    }
}

// ---------------- trajectory assembly ----------------
__global__ void traj_kernel(const float* __restrict__ p, const float* __restrict__ dict,
                            float* __restrict__ out)
{
    int b = blockIdx.x;
    __shared__ float sx[SSEG], sy[SSEG], s1[SSEG], s2[SSEG];
    __shared__ int sidx[SSEG];

    if (threadIdx.x == 0) {
        float cx = p[b * OUTDIM + 0];
        float cy = p[b * OUTDIM + 1];
        for (int s = 0; s < SSEG; s++) {
            float f0  = p[b * OUTDIM + 2 + s * 3 + 0];
            float sc1 = p[b * OUTDIM + 2 + s * 3 + 1];
            float sc2 = p[b * OUTDIM + 2 + s * 3 + 2];
            float r = rintf(f0);
            r = fminf(fmaxf(r, 0.0f), (float)(DDICT - 1));
            int id = (int)r;
            sidx[s] = id; s1[s] = sc1; s2[s] = sc2;
            sx[s] = cx; sy[s] = cy;
            cx += dict[((size_t)id * LSEG + (LSEG - 1)) * 2 + 0] * sc1;
            cy += dict[((size_t)id * LSEG + (LSEG - 1)) * 2 + 1] * sc2;
        }
    }
    __syncthreads();

    for (int i = threadIdx.x; i < SSEG * LSEG; i += blockDim.x) {
        int s = i / LSEG, l = i % LSEG;
        int id = sidx[s];
        float bx = dict[((size_t)id * LSEG + l) * 2 + 0];
        float by = dict[((size_t)id * LSEG + l) * 2 + 1];
        out[((size_t)b * SSEG * LSEG + i) * 2 + 0] = fmaf(bx, s1[s], sx[s]);
        out[((size_t)b * SSEG * LSEG + i) * 2 + 1] = fmaf(by, s2[s], sy[s]);
    }
}

// ---------------- launch ----------------
extern "C" void kernel_launch(void* const* d_in, const int* in_sizes, int n_in,
                              void* d_out, int out_size)
{
    const float* x   = (const float*)d_in[0];
    const float* w1  = (const float*)d_in[1];
    const float* b1  = (const float*)d_in[2];
    const float* w2  = (const float*)d_in[3];
    const float* b2  = (const float*)d_in[4];
    const float* w3  = (const float*)d_in[5];
    const float* b3  = (const float*)d_in[6];
    const float* w4  = (const float*)d_in[7];
    const float* b4  = (const float*)d_in[8];
    const float* fw1 = (const float*)d_in[9];
    const float* fb1 = (const float*)d_in[10];
    const float* fw2 = (const float*)d_in[11];
    const float* fb2 = (const float*)d_in[12];
    const float* fw3 = (const float*)d_in[13];
    const float* fb3 = (const float*)d_in[14];
    const float* dict= (const float*)d_in[15];
    float* out = (float*)d_out;

    float *h1, *h2, *h3, *h4, *a1, *a2, *pp, *part, *w1k;
    __half *w2h, *w2l, *w3h, *w3l, *w4h, *w4l;
    cudaGetSymbolAddress((void**)&h1,  g_h1);
    cudaGetSymbolAddress((void**)&h2,  g_h2);
    cudaGetSymbolAddress((void**)&h3,  g_h3);
    cudaGetSymbolAddress((void**)&h4,  g_h4);
    cudaGetSymbolAddress((void**)&a1,  g_a1);
    cudaGetSymbolAddress((void**)&a2,  g_a2);
    cudaGetSymbolAddress((void**)&pp,  g_p);
    cudaGetSymbolAddress((void**)&part,g_part);
    cudaGetSymbolAddress((void**)&w1k, g_w1k);
    cudaGetSymbolAddress((void**)&w2h, g_w2h);
    cudaGetSymbolAddress((void**)&w2l, g_w2l);
    cudaGetSymbolAddress((void**)&w3h, g_w3h);
    cudaGetSymbolAddress((void**)&w3l, g_w3l);
    cudaGetSymbolAddress((void**)&w4h, g_w4h);
    cudaGetSymbolAddress((void**)&w4l, g_w4l);

    // dyn smem: max(8 double-buffered half-tiles = 81920 B, epilogue 67584 B)
    const int SMEM_DYN = 8 * 128 * 40 * 2;   // 81920
    cudaFuncSetAttribute((const void*)conv_mma<64,49,49,128,2>,
                         cudaFuncAttributeMaxDynamicSharedMemorySize, SMEM_DYN);
    cudaFuncSetAttribute((const void*)conv_mma<128,23,23,256,4>,
                         cudaFuncAttributeMaxDynamicSharedMemorySize, SMEM_DYN);
    cudaFuncSetAttribute((const void*)conv_mma<256,10,10,512,8>,
                         cudaFuncAttributeMaxDynamicSharedMemorySize, SMEM_DYN);

    // weight repacks
    repack_wk<<<(64*3*9 + 255) / 256, 256>>>(w1, w1k, 3, 64);
    repack_h2<<<(128*64*9  + 255) / 256, 256>>>(w2, w2h, w2l, 64,  128);
    repack_h2<<<(256*128*9 + 255) / 256, 256>>>(w3, w3h, w3l, 128, 256);
    repack_h2<<<(512*256*9 + 255) / 256, 256>>>(w4, w4h, w4l, 256, 512);

    // stage 1 (scalar FFMA2): (128,3,100,100) -> (128,64,49,49)
    {
        int total = NB * (64/8) * 49 * 49;
        conv_pool_relu2<3,100,100,49,49,64><<<(total + 255) / 256, 256>>>(x, w1k, b1, h1);
    }
    // stage 2 (fp16-split mma, double-buffered): -> (128,128,23,23)
    conv_mma<64,49,49,128,2><<<dim3(23, NB, 1), 256, SMEM_DYN>>>(h1, w2h, w2l, b2, h2);
    // stage 3: -> (128,256,10,10)
    conv_mma<128,23,23,256,4><<<dim3(5, NB, 2), 256, SMEM_DYN>>>(h2, w3h, w3l, b3, h3);
    // stage 4: -> (128,512,4,4)
    conv_mma<256,10,10,512,8><<<dim3(1, NB, 4), 256, SMEM_DYN>>>(h3, w4h, w4l, b4, h4);

    // fc1: (128,8192) @ (8192,2048) + tanh, split-K=2
    {
        dim3 grid(2048 / 64, NB / 64, 2);
        gemm64_part<<<grid, 256>>>(h4, fw1, part, NB, 2048, 8192, 4096);
        combine_tanh<<<(NB * 2048 + 255) / 256, 256>>>(part, fb1, a1, NB, 2048);
    }
    // fc2: (128,2048) @ (2048,2048) + tanh, split-K=2
    {
        dim3 grid(2048 / 64, NB / 64, 2);
        gemm64_part<<<grid, 256>>>(a1, fw2, part, NB, 2048, 2048, 1024);
        combine_tanh<<<(NB * 2048 + 255) / 256, 256>>>(part, fb2, a2, NB, 2048);
    }
    // fc3: (128,2048) @ (2048,62)
    fc_small<<<NB, 256>>>(a2, fw3, fb3, pp, OUTDIM, 2048);

    // trajectory assembly -> (128, 4000, 2)
    traj_kernel<<<NB, 256>>>(pp, dict, out);
}